// round 12
// baseline (speedup 1.0000x reference)
#include <cuda_runtime.h>
#include <cuda_fp16.h>
#include <cstdint>
#include <cstdio>

#define BATCH 2
#define HEADS 8
#define DH 64
#define NSEQ 2304
#define DIM 512
#define GRID48 48
#define LOG2E 1.4426950408889634f
#define QPRE (0.125f * LOG2E)

// ================= scratch (static device globals; no allocations) =================
__device__ __align__(256) float g_bias[95 * 95];   // cos(phase)*0.1*log2(e)

__device__ __align__(256) __half g_xh[(size_t)BATCH * NSEQ * DIM];    // [b][n][c]
__device__ __align__(256) __half g_wqh[(size_t)3 * DIM * DIM];        // [d][c]
__device__ __align__(256) __half g_woh[(size_t)DIM * DIM];            // [o][c]
__device__ __align__(256) __half g_qh[(size_t)BATCH * HEADS * NSEQ * DH];  // prescaled
__device__ __align__(256) __half g_kh[(size_t)BATCH * HEADS * NSEQ * DH];
__device__ __align__(256) __half g_vh[(size_t)BATCH * HEADS * NSEQ * DH];
__device__ __align__(256) __half g_aoh[(size_t)BATCH * NSEQ * DIM];   // [b*n][c]

// split-K attention partials (fp32, unnormalized)
__device__ __align__(256) float g_opart[(size_t)2 * BATCH * HEADS * NSEQ * DH];
__device__ __align__(256) float g_lrp[(size_t)2 * BATCH * HEADS * NSEQ];

// ================= helpers =================
__device__ __forceinline__ uint32_t smem_u32(const void* p) {
    uint32_t a;
    asm("{ .reg .u64 t; cvta.to.shared.u64 t, %1; cvt.u32.u64 %0, t; }" : "=r"(a) : "l"(p));
    return a;
}
__device__ __forceinline__ void ldsm_x4(uint32_t& r0, uint32_t& r1, uint32_t& r2, uint32_t& r3,
                                        uint32_t addr) {
    asm volatile("ldmatrix.sync.aligned.m8n8.x4.shared.b16 {%0,%1,%2,%3}, [%4];"
                 : "=r"(r0), "=r"(r1), "=r"(r2), "=r"(r3) : "r"(addr));
}
__device__ __forceinline__ void ldsm_x4t(uint32_t& r0, uint32_t& r1, uint32_t& r2, uint32_t& r3,
                                         uint32_t addr) {
    asm volatile("ldmatrix.sync.aligned.m8n8.x4.trans.shared.b16 {%0,%1,%2,%3}, [%4];"
                 : "=r"(r0), "=r"(r1), "=r"(r2), "=r"(r3) : "r"(addr));
}
__device__ __forceinline__ void mma16816h(float* c, uint32_t a0, uint32_t a1, uint32_t a2,
                                          uint32_t a3, uint32_t b0, uint32_t b1) {
    asm volatile(
        "mma.sync.aligned.m16n8k16.row.col.f32.f16.f16.f32 "
        "{%0,%1,%2,%3}, {%4,%5,%6,%7}, {%8,%9}, {%0,%1,%2,%3};"
        : "+f"(c[0]), "+f"(c[1]), "+f"(c[2]), "+f"(c[3])
        : "r"(a0), "r"(a1), "r"(a2), "r"(a3), "r"(b0), "r"(b1));
}
__device__ __forceinline__ uint32_t pack2h(float x, float y) {
    uint32_t r;
    asm("cvt.rn.f16x2.f32 %0, %1, %2;" : "=r"(r) : "f"(y), "f"(x));
    return r;
}
__device__ __forceinline__ float ex2(float x) {
    float y;
    asm("ex2.approx.f32 %0, %1;" : "=f"(y) : "f"(x));
    return y;
}
__device__ __forceinline__ void cp16(uint32_t s, const void* g) {
    asm volatile("cp.async.cg.shared.global [%0], [%1], 16;" :: "r"(s), "l"(g));
}
__device__ __forceinline__ void cp_commit() {
    asm volatile("cp.async.commit_group;" ::: "memory");
}
template <int N>
__device__ __forceinline__ void cp_wait() {
    asm volatile("cp.async.wait_group %0;" :: "n"(N) : "memory");
}

// ================= dense GEMM: CTA 128(m) x 64(n), warp 32x32, 3-stage ring =================
#define TSA 40
#define A_HALVES (128 * TSA)
#define B_HALVES (64 * TSA)
#define STG_HALVES (A_HALVES + B_HALVES)
#define STG_BYTES (STG_HALVES * 2)       // 15360
#define GSM_TOTAL (3 * STG_BYTES)        // 46080

__device__ __forceinline__ void gemm_core_h(
    const __half* __restrict__ A, const __half* __restrict__ B,
    __half* smf, float c[2][4][4])
{
    const int tid = threadIdx.x;
    const int wid = tid >> 5;
    const int lane = tid & 31;
    const int wm = wid & 3, wn = wid >> 2;
    const uint32_t base = smem_u32(smf);

    uint32_t aAddr[2][2], bAddr[2][2];
    {
        int aRow = wm * 32 + (lane & 15);
        int aCol = (lane >> 4) * 8;
        #pragma unroll
        for (int mf = 0; mf < 2; mf++)
            #pragma unroll
            for (int ks = 0; ks < 2; ks++)
                aAddr[mf][ks] = base + ((aRow + mf * 16) * TSA + ks * 16 + aCol) * 2;
        int bRow = wn * 32 + (lane & 7) + ((lane >> 4) << 3);
        int bCol = ((lane >> 3) & 1) << 3;
        #pragma unroll
        for (int np = 0; np < 2; np++)
            #pragma unroll
            for (int ks = 0; ks < 2; ks++)
                bAddr[np][ks] = base + A_HALVES * 2 +
                                ((bRow + np * 16) * TSA + ks * 16 + bCol) * 2;
    }

    const int ldRow = tid >> 2;     // 0..63
    const int ldSeg = tid & 3;

    auto stage = [&](int ch, int par) {
        const int c0 = ch * 32;
        const uint32_t bb = base + par * STG_BYTES;
        cp16(bb + (ldRow * TSA + ldSeg * 8) * 2,
             A + (size_t)ldRow * DIM + c0 + ldSeg * 8);
        cp16(bb + ((ldRow + 64) * TSA + ldSeg * 8) * 2,
             A + (size_t)(ldRow + 64) * DIM + c0 + ldSeg * 8);
        cp16(bb + A_HALVES * 2 + (ldRow * TSA + ldSeg * 8) * 2,
             B + (size_t)ldRow * DIM + c0 + ldSeg * 8);
    };

    stage(0, 0); cp_commit();
    stage(1, 1); cp_commit();

    #pragma unroll
    for (int ch = 0; ch < 16; ch++) {
        if (ch < 15) cp_wait<1>(); else cp_wait<0>();
        __syncthreads();
        if (ch < 14) {
            stage(ch + 2, (ch + 2) % 3);
            cp_commit();
        }

        const uint32_t bo = (uint32_t)((ch % 3) * STG_BYTES);
        #pragma unroll
        for (int ks = 0; ks < 2; ks++) {
            uint32_t aa[2][4];
            #pragma unroll
            for (int mf = 0; mf < 2; mf++)
                ldsm_x4(aa[mf][0], aa[mf][1], aa[mf][2], aa[mf][3], aAddr[mf][ks] + bo);
            uint32_t bb[4][2];
            #pragma unroll
            for (int np = 0; np < 2; np++)
                ldsm_x4(bb[2 * np][0], bb[2 * np][1], bb[2 * np + 1][0], bb[2 * np + 1][1],
                        bAddr[np][ks] + bo);
            #pragma unroll
            for (int mf = 0; mf < 2; mf++)
                #pragma unroll
                for (int nf = 0; nf < 4; nf++)
                    mma16816h(c[mf][nf], aa[mf][0], aa[mf][1], aa[mf][2], aa[mf][3],
                              bb[nf][0], bb[nf][1]);
        }
    }
}

// ================= QKV GEMM (fp16) =================
__global__ __launch_bounds__(256, 3) void qkv_mma_kernel() {
    extern __shared__ __align__(16) __half smf_q[];

    const int d0 = blockIdx.x * 64;
    const int n0 = blockIdx.y * 128;
    const int b  = blockIdx.z;

    float c[2][4][4] = {};
    gemm_core_h(g_xh + ((size_t)b * NSEQ + n0) * DIM,
                g_wqh + (size_t)d0 * DIM, smf_q, c);

    const int tid = threadIdx.x;
    const int wid = tid >> 5, lane = tid & 31;
    const int wm = wid & 3, wn = wid >> 2;
    #pragma unroll
    for (int mf = 0; mf < 2; mf++)
        #pragma unroll
        for (int nf = 0; nf < 4; nf++) {
            int dglob = d0 + wn * 32 + nf * 8 + 2 * (lane & 3);
            const int part = dglob >> 9;
            const int head = (dglob >> 6) & 7;
            const int dh = dglob & 63;
            __half* gb = (part == 0) ? g_qh : (part == 1) ? g_kh : g_vh;
            const float s = (part == 0) ? QPRE : 1.0f;
            int n = n0 + wm * 32 + mf * 16 + (lane >> 2);
            size_t idx = ((size_t)(b * HEADS + head) * NSEQ + n) * DH + dh;
            *(uint32_t*)&gb[idx] = pack2h(c[mf][nf][0] * s, c[mf][nf][1] * s);
            *(uint32_t*)&gb[idx + 8 * DH] = pack2h(c[mf][nf][2] * s, c[mf][nf][3] * s);
        }
}

// ================= Output projection (fp16) =================
__global__ __launch_bounds__(256, 3) void out_mma_kernel(const float* __restrict__ bias,
                                                         float* __restrict__ out) {
    extern __shared__ __align__(16) __half smf_o[];

    const int o0 = blockIdx.x * 64;
    const int n0 = blockIdx.y * 128;
    const int b  = blockIdx.z;

    float c[2][4][4] = {};
    gemm_core_h(g_aoh + ((size_t)b * NSEQ + n0) * DIM,
                g_woh + (size_t)o0 * DIM, smf_o, c);

    const int tid = threadIdx.x;
    const int wid = tid >> 5, lane = tid & 31;
    const int wm = wid & 3, wn = wid >> 2;
    #pragma unroll
    for (int nf = 0; nf < 4; nf++) {
        int o = o0 + wn * 32 + nf * 8 + 2 * (lane & 3);
        float b0v = __ldg(&bias[o]);
        float b1v = __ldg(&bias[o + 1]);
        #pragma unroll
        for (int mf = 0; mf < 2; mf++) {
            int n = n0 + wm * 32 + mf * 16 + (lane >> 2);
            float* p0 = out + (size_t)(b * DIM + o) * NSEQ + n;
            float* p1 = p0 + NSEQ;
            p0[0] = c[mf][nf][0] + b0v;
            p1[0] = c[mf][nf][1] + b1v;
            p0[8] = c[mf][nf][2] + b0v;
            p1[8] = c[mf][nf][3] + b1v;
        }
    }
}

// ================= prep: weight fp16 convert + Fresnel bias table =================
__global__ void prep_kernel(const float* __restrict__ wqkv,
                            const float* __restrict__ wout,
                            const float* __restrict__ wl) {
    int g = blockIdx.x * blockDim.x + threadIdx.x;
    int i = g * 4;
    if (i < 3 * DIM * DIM) {
        float4 f = *(const float4*)(wqkv + i);
        *(uint2*)&g_wqh[i] = make_uint2(pack2h(f.x, f.y), pack2h(f.z, f.w));
    }
    if (i < DIM * DIM) {
        float4 f = *(const float4*)(wout + i);
        *(uint2*)&g_woh[i] = make_uint2(pack2h(f.x, f.y), pack2h(f.z, f.w));
    }
    if (g < 95 * 95) {
        int dy = g / 95 - 47;
        int dx = g % 95 - 47;
        double dist = sqrt((double)(dy * dy + dx * dx) + 1e-8);
        double denom = fabs((double)wl[0]) * 48.0 + 1e-6;
        double phase = 6.283185307179586476925286766559 * dist / denom;
        g_bias[g] = (float)(cos(phase) * 0.1 * 1.4426950408889634074);
    }
}

// x[b][c][n] fp32 -> g_xh[b][n][c] fp16 (transpose + convert)
__global__ void split_x_kernel(const float* __restrict__ x) {
    __shared__ float t[32][33];
    const int b = blockIdx.z;
    const int n0 = blockIdx.x * 32;
    const int c0 = blockIdx.y * 32;
    const int tx = threadIdx.x, ty = threadIdx.y;
    #pragma unroll
    for (int r = ty; r < 32; r += 8)
        t[r][tx] = x[((size_t)b * DIM + c0 + r) * NSEQ + n0 + tx];
    __syncthreads();
    #pragma unroll
    for (int r = ty; r < 32; r += 8)
        g_xh[((size_t)b * NSEQ + n0 + r) * DIM + c0 + tx] = __float2half_rn(t[tx][r]);
}

// ================= Flash attention, split-K by 2 (fp16, single-buffer KV) =================
#define KVST 72            // row stride in halves (144B -> conflict-free ldmatrix)
#define KBUF 18432         // one K (or V) buffer: 128*72*2
#define SMA_BIAS 0         // 51 bias rows window: 4848 floats -> 19392 B
#define SMA_KIDX 19392     // 2304 u16 -> 4608 B
#define SMA_KV 24000       // K (18432) + V (18432)
#define SMA_TOTAL (SMA_KV + 2 * KBUF)    // 60864 B -> 3 CTAs/SM

__global__ __launch_bounds__(256, 3) void attn_mma_kernel() {
    extern __shared__ __align__(16) char smc[];
    float* sBias = (float*)(smc + SMA_BIAS);
    uint16_t* sKidx = (uint16_t*)(smc + SMA_KIDX);

    const int tid = threadIdx.x;
    const int w = tid >> 5, lane = tid & 31;
    const int n0 = blockIdx.x * 128;
    const int h = blockIdx.y;
    const int b = blockIdx.z >> 1;
    const int kvh = blockIdx.z & 1;          // KV half: keys [kvh*1152, +1152)
    const int gr = lane >> 2, c2 = 2 * (lane & 3);

    const __half* Kg = g_kh + (size_t)(b * HEADS + h) * NSEQ * DH;
    const __half* Vg = g_vh + (size_t)(b * HEADS + h) * NSEQ * DH;
    const uint32_t kvB = smem_u32(smc + SMA_KV);

    auto stageKV = [&](int k0) {
        const int j = tid >> 1, d0 = (tid & 1) * 32;
        const __half* kr = Kg + (size_t)(k0 + j) * DH + d0;
        const __half* vr = Vg + (size_t)(k0 + j) * DH + d0;
        uint32_t sk = kvB + (j * KVST + d0) * 2;
        uint32_t sv = sk + KBUF;
        #pragma unroll
        for (int i = 0; i < 4; i++) {
            cp16(sk + 16 * i, kr + 8 * i);
            cp16(sv + 16 * i, vr + 8 * i);
        }
    };

    const int kbase = kvh * (NSEQ / 2);
    stageKV(kbase); cp_commit();

    const int qyA = n0 / GRID48;
    const int nb = min(4848, 9025 - qyA * 95);
    for (int i = tid; i < nb; i += 256) sBias[i] = g_bias[qyA * 95 + i];
    for (int i = tid; i < NSEQ; i += 256) sKidx[i] = (uint16_t)(i + 47 * (i / GRID48));

    uint32_t qf[4][4];
    {
        const __half* Qg = g_qh + ((size_t)(b * HEADS + h) * NSEQ + n0 + 16 * w) * DH;
        #pragma unroll
        for (int kk = 0; kk < 4; kk++)
            #pragma unroll
            for (int hf = 0; hf < 2; hf++) {
                int d = kk * 16 + hf * 8 + c2;
                qf[kk][hf * 2 + 0] = *(const uint32_t*)(Qg + (size_t)gr * DH + d);
                qf[kk][hf * 2 + 1] = *(const uint32_t*)(Qg + (size_t)(gr + 8) * DH + d);
            }
    }

    const int qr0 = n0 + 16 * w + gr;
    const int qb0 = (qr0 / GRID48 - qyA) * 95 + (qr0 % GRID48) + 4512;
    const int qr1 = qr0 + 8;
    const int qb1 = (qr1 / GRID48 - qyA) * 95 + (qr1 % GRID48) + 4512;

    const int rB = (lane & 7) + ((lane >> 4) << 3);
    const int cB = ((lane >> 3) & 1) << 3;
    const int rV = lane & 15;
    const int cV = (lane >> 4) << 3;
    const uint32_t kB = kvB;
    const uint32_t vB = kvB + KBUF;

    float o[8][4] = {};
    float lr0 = 0.f, lr1 = 0.f;

    for (int t = 0; t < NSEQ / 256; t++) {       // 9 tiles of 128 keys
        if (t > 0) {
            __syncthreads();                     // previous compute done
            stageKV(kbase + t * 128);
            cp_commit();
        }
        cp_wait<0>();
        __syncthreads();

        const int k0 = kbase + t * 128;

        #pragma unroll
        for (int j = 0; j < 8; j++) {
            // ---- S = Q K^T (K fragments loaded in halves: 8 regs live) ----
            float s0[4] = {0.f, 0.f, 0.f, 0.f};
            float s1[4] = {0.f, 0.f, 0.f, 0.f};
            {
                uint32_t kb2[2][4];
                #pragma unroll
                for (int kh2 = 0; kh2 < 2; kh2++) {
                    #pragma unroll
                    for (int kk = 0; kk < 2; kk++) {
                        uint32_t off = (uint32_t)(((j * 16 + rB) * KVST +
                                                   (kh2 * 2 + kk) * 16 + cB) * 2);
                        ldsm_x4(kb2[kk][0], kb2[kk][1], kb2[kk][2], kb2[kk][3], kB + off);
                    }
                    #pragma unroll
                    for (int kk = 0; kk < 2; kk++) {
                        int kq = kh2 * 2 + kk;
                        mma16816h(s0, qf[kq][0], qf[kq][1], qf[kq][2], qf[kq][3],
                                  kb2[kk][0], kb2[kk][1]);
                        mma16816h(s1, qf[kq][0], qf[kq][1], qf[kq][2], qf[kq][3],
                                  kb2[kk][2], kb2[kk][3]);
                    }
                }
            }

            // ---- bias + exp2 + pack P (kidx via paired u32 loads) ----
            int kj0 = k0 + 16 * j + c2;
            uint32_t pr0 = *(const uint32_t*)(sKidx + kj0);
            uint32_t pr1 = *(const uint32_t*)(sKidx + kj0 + 8);
            int ka0 = pr0 & 0xffff, ka1 = pr0 >> 16;
            int kb0 = pr1 & 0xffff, kb1 = pr1 >> 16;
            float p0 = ex2(s0[0] + sBias[qb0 - ka0]);
            float p1 = ex2(s0[1] + sBias[qb0 - ka1]);
            float p2 = ex2(s0[2] + sBias[qb1 - ka0]);
            float p3 = ex2(s0[3] + sBias[qb1 - ka1]);
            float p4 = ex2(s1[0] + sBias[qb0 - kb0]);
            float p5 = ex2(s1[1] + sBias[qb0 - kb1]);
            float p6 = ex2(s1[2] + sBias[qb1 - kb0]);
            float p7 = ex2(s1[3] + sBias[qb1 - kb1]);
            lr0 += p0 + p1 + p4 + p5;
            lr1 += p2 + p3 + p6 + p7;
            uint32_t pa0 = pack2h(p0, p1), pa1 = pack2h(p2, p3);
            uint32_t pa2 = pack2h(p4, p5), pa3 = pack2h(p6, p7);

            // ---- O += P V (V fragments in halves) ----
            {
                uint32_t vb2[2][4];
                #pragma unroll
                for (int vh2 = 0; vh2 < 2; vh2++) {
                    #pragma unroll
                    for (int nf2 = 0; nf2 < 2; nf2++) {
                        uint32_t off = (uint32_t)(((j * 16 + rV) * KVST +
                                                   (vh2 * 2 + nf2) * 16 + cV) * 2);
                        ldsm_x4t(vb2[nf2][0], vb2[nf2][1], vb2[nf2][2], vb2[nf2][3],
                                 vB + off);
                    }
                    #pragma unroll
                    for (int nf2 = 0; nf2 < 2; nf2++) {
                        int no = (vh2 * 2 + nf2) * 2;
                        mma16816h(o[no], pa0, pa1, pa2, pa3, vb2[nf2][0], vb2[nf2][1]);
                        mma16816h(o[no + 1], pa0, pa1, pa2, pa3, vb2[nf2][2], vb2[nf2][3]);
                    }
                }
            }
        }
    }

    // ---- quad-reduce lr, write fp32 partials ----
    lr0 += __shfl_xor_sync(0xffffffffu, lr0, 1);
    lr0 += __shfl_xor_sync(0xffffffffu, lr0, 2);
    lr1 += __shfl_xor_sync(0xffffffffu, lr1, 1);
    lr1 += __shfl_xor_sync(0xffffffffu, lr1, 2);

    size_t pbase = ((size_t)(kvh * BATCH + b) * HEADS + h) * NSEQ;
    if ((lane & 3) == 0) {
        g_lrp[pbase + qr0] = lr0;
        g_lrp[pbase + qr1] = lr1;
    }
    float* op0 = g_opart + (pbase + qr0) * DH;
    float* op1 = g_opart + (pbase + qr1) * DH;
    #pragma unroll
    for (int nf = 0; nf < 8; nf++) {
        *(float2*)&op0[8 * nf + c2] = make_float2(o[nf][0], o[nf][1]);
        *(float2*)&op1[8 * nf + c2] = make_float2(o[nf][2], o[nf][3]);
    }
}

// ================= split-K reduce: combine halves, normalize, write fp16 g_aoh =================
__global__ __launch_bounds__(256) void attn_reduce_kernel() {
    const int idx = blockIdx.x * 256 + threadIdx.x;  // covers NSEQ * (DH/4)
    const int h = blockIdx.y, b = blockIdx.z;
    const int n = idx >> 4;
    const int dh = (idx & 15) * 4;
    const size_t HST = (size_t)BATCH * HEADS * NSEQ;

    size_t base = ((size_t)b * HEADS + h) * NSEQ + n;
    float lr = g_lrp[base] + g_lrp[HST + base];
    float inv = 1.0f / lr;
    float4 a = *(const float4*)&g_opart[base * DH + dh];
    float4 c = *(const float4*)&g_opart[(HST + base) * DH + dh];
    *(uint2*)&g_aoh[((size_t)b * NSEQ + n) * DIM + h * DH + dh] =
        make_uint2(pack2h((a.x + c.x) * inv, (a.y + c.y) * inv),
                   pack2h((a.z + c.z) * inv, (a.w + c.w) * inv));
}

// ================= launch =================
extern "C" void kernel_launch(void* const* d_in, const int* in_sizes, int n_in,
                              void* d_out, int out_size) {
    const float* x     = (const float*)d_in[0];
    const float* w_qkv = (const float*)d_in[1];
    const float* w_out = (const float*)d_in[2];
    const float* b_out = (const float*)d_in[3];
    const float* wl    = (const float*)d_in[4];
    float* out = (float*)d_out;

    (void)in_sizes; (void)n_in; (void)out_size;

    cudaFuncSetAttribute(attn_mma_kernel,
                         cudaFuncAttributeMaxDynamicSharedMemorySize, SMA_TOTAL);
    cudaFuncSetAttribute(qkv_mma_kernel,
                         cudaFuncAttributeMaxDynamicSharedMemorySize, GSM_TOTAL);
    cudaFuncSetAttribute(out_mma_kernel,
                         cudaFuncAttributeMaxDynamicSharedMemorySize, GSM_TOTAL);

    split_x_kernel<<<dim3(NSEQ / 32, DIM / 32, BATCH), dim3(32, 8)>>>(x);
    prep_kernel<<<(3 * DIM * DIM / 4 + 255) / 256, 256>>>(w_qkv, w_out, wl);

    qkv_mma_kernel<<<dim3(3 * DIM / 64, NSEQ / 128, BATCH), 256, GSM_TOTAL>>>();
    attn_mma_kernel<<<dim3(NSEQ / 128, HEADS, BATCH * 2), 256, SMA_TOTAL>>>();
    attn_reduce_kernel<<<dim3(NSEQ * (DH / 4) / 256, HEADS, BATCH), 256>>>();
    out_mma_kernel<<<dim3(DIM / 64, NSEQ / 128, BATCH), 256, GSM_TOTAL>>>(b_out, out);
}

// round 13
// speedup vs baseline: 1.1075x; 1.1075x over previous
#include <cuda_runtime.h>
#include <cuda_fp16.h>
#include <cstdint>
#include <cstdio>

#define BATCH 2
#define HEADS 8
#define DH 64
#define NSEQ 2304
#define DIM 512
#define GRID48 48
#define LOG2E 1.4426950408889634f
#define QPRE (0.125f * LOG2E)

// ================= scratch (static device globals; no allocations) =================
__device__ __align__(256) float g_bias[95 * 95];   // cos(phase)*0.1*log2(e)

__device__ __align__(256) __half g_xh[(size_t)BATCH * NSEQ * DIM];    // [b][n][c]
__device__ __align__(256) __half g_wqh[(size_t)3 * DIM * DIM];        // [d][c]
__device__ __align__(256) __half g_woh[(size_t)DIM * DIM];            // [o][c]
__device__ __align__(256) __half g_qh[(size_t)BATCH * HEADS * NSEQ * DH];  // prescaled
__device__ __align__(256) __half g_kh[(size_t)BATCH * HEADS * NSEQ * DH];
__device__ __align__(256) __half g_vh[(size_t)BATCH * HEADS * NSEQ * DH];
__device__ __align__(256) __half g_aoh[(size_t)BATCH * NSEQ * DIM];   // [b*n][c]

// ================= helpers =================
__device__ __forceinline__ uint32_t smem_u32(const void* p) {
    uint32_t a;
    asm("{ .reg .u64 t; cvta.to.shared.u64 t, %1; cvt.u32.u64 %0, t; }" : "=r"(a) : "l"(p));
    return a;
}
__device__ __forceinline__ void ldsm_x4(uint32_t& r0, uint32_t& r1, uint32_t& r2, uint32_t& r3,
                                        uint32_t addr) {
    asm volatile("ldmatrix.sync.aligned.m8n8.x4.shared.b16 {%0,%1,%2,%3}, [%4];"
                 : "=r"(r0), "=r"(r1), "=r"(r2), "=r"(r3) : "r"(addr));
}
__device__ __forceinline__ void ldsm_x4t(uint32_t& r0, uint32_t& r1, uint32_t& r2, uint32_t& r3,
                                         uint32_t addr) {
    asm volatile("ldmatrix.sync.aligned.m8n8.x4.trans.shared.b16 {%0,%1,%2,%3}, [%4];"
                 : "=r"(r0), "=r"(r1), "=r"(r2), "=r"(r3) : "r"(addr));
}
__device__ __forceinline__ void mma16816h(float* c, uint32_t a0, uint32_t a1, uint32_t a2,
                                          uint32_t a3, uint32_t b0, uint32_t b1) {
    asm volatile(
        "mma.sync.aligned.m16n8k16.row.col.f32.f16.f16.f32 "
        "{%0,%1,%2,%3}, {%4,%5,%6,%7}, {%8,%9}, {%0,%1,%2,%3};"
        : "+f"(c[0]), "+f"(c[1]), "+f"(c[2]), "+f"(c[3])
        : "r"(a0), "r"(a1), "r"(a2), "r"(a3), "r"(b0), "r"(b1));
}
__device__ __forceinline__ uint32_t pack2h(float x, float y) {
    uint32_t r;
    asm("cvt.rn.f16x2.f32 %0, %1, %2;" : "=r"(r) : "f"(y), "f"(x));
    return r;
}
__device__ __forceinline__ float ex2(float x) {
    float y;
    asm("ex2.approx.f32 %0, %1;" : "=f"(y) : "f"(x));
    return y;
}
__device__ __forceinline__ void cp16(uint32_t s, const void* g) {
    asm volatile("cp.async.cg.shared.global [%0], [%1], 16;" :: "r"(s), "l"(g));
}
__device__ __forceinline__ void cp_commit() {
    asm volatile("cp.async.commit_group;" ::: "memory");
}
template <int N>
__device__ __forceinline__ void cp_wait() {
    asm volatile("cp.async.wait_group %0;" :: "n"(N) : "memory");
}

// ================= dense GEMM: CTA 128(m) x 64(n), warp 32x32, 3-stage ring =================
#define TSA 40
#define A_HALVES (128 * TSA)
#define B_HALVES (64 * TSA)
#define STG_HALVES (A_HALVES + B_HALVES)
#define STG_BYTES (STG_HALVES * 2)       // 15360
#define GSM_TOTAL (3 * STG_BYTES)        // 46080

__device__ __forceinline__ void gemm_core_h(
    const __half* __restrict__ A, const __half* __restrict__ B,
    __half* smf, float c[2][4][4])
{
    const int tid = threadIdx.x;
    const int wid = tid >> 5;
    const int lane = tid & 31;
    const int wm = wid & 3, wn = wid >> 2;
    const uint32_t base = smem_u32(smf);

    uint32_t aAddr[2][2], bAddr[2][2];
    {
        int aRow = wm * 32 + (lane & 15);
        int aCol = (lane >> 4) * 8;
        #pragma unroll
        for (int mf = 0; mf < 2; mf++)
            #pragma unroll
            for (int ks = 0; ks < 2; ks++)
                aAddr[mf][ks] = base + ((aRow + mf * 16) * TSA + ks * 16 + aCol) * 2;
        int bRow = wn * 32 + (lane & 7) + ((lane >> 4) << 3);
        int bCol = ((lane >> 3) & 1) << 3;
        #pragma unroll
        for (int np = 0; np < 2; np++)
            #pragma unroll
            for (int ks = 0; ks < 2; ks++)
                bAddr[np][ks] = base + A_HALVES * 2 +
                                ((bRow + np * 16) * TSA + ks * 16 + bCol) * 2;
    }

    const int ldRow = tid >> 2;     // 0..63
    const int ldSeg = tid & 3;

    auto stage = [&](int ch, int par) {
        const int c0 = ch * 32;
        const uint32_t bb = base + par * STG_BYTES;
        cp16(bb + (ldRow * TSA + ldSeg * 8) * 2,
             A + (size_t)ldRow * DIM + c0 + ldSeg * 8);
        cp16(bb + ((ldRow + 64) * TSA + ldSeg * 8) * 2,
             A + (size_t)(ldRow + 64) * DIM + c0 + ldSeg * 8);
        cp16(bb + A_HALVES * 2 + (ldRow * TSA + ldSeg * 8) * 2,
             B + (size_t)ldRow * DIM + c0 + ldSeg * 8);
    };

    stage(0, 0); cp_commit();
    stage(1, 1); cp_commit();

    #pragma unroll
    for (int ch = 0; ch < 16; ch++) {
        if (ch < 15) cp_wait<1>(); else cp_wait<0>();
        __syncthreads();
        if (ch < 14) {
            stage(ch + 2, (ch + 2) % 3);
            cp_commit();
        }

        const uint32_t bo = (uint32_t)((ch % 3) * STG_BYTES);
        #pragma unroll
        for (int ks = 0; ks < 2; ks++) {
            uint32_t aa[2][4];
            #pragma unroll
            for (int mf = 0; mf < 2; mf++)
                ldsm_x4(aa[mf][0], aa[mf][1], aa[mf][2], aa[mf][3], aAddr[mf][ks] + bo);
            uint32_t bb[4][2];
            #pragma unroll
            for (int np = 0; np < 2; np++)
                ldsm_x4(bb[2 * np][0], bb[2 * np][1], bb[2 * np + 1][0], bb[2 * np + 1][1],
                        bAddr[np][ks] + bo);
            #pragma unroll
            for (int mf = 0; mf < 2; mf++)
                #pragma unroll
                for (int nf = 0; nf < 4; nf++)
                    mma16816h(c[mf][nf], aa[mf][0], aa[mf][1], aa[mf][2], aa[mf][3],
                              bb[nf][0], bb[nf][1]);
        }
    }
}

// ================= QKV GEMM (fp16) =================
__global__ __launch_bounds__(256, 3) void qkv_mma_kernel() {
    extern __shared__ __align__(16) __half smf_q[];

    const int d0 = blockIdx.x * 64;
    const int n0 = blockIdx.y * 128;
    const int b  = blockIdx.z;

    float c[2][4][4] = {};
    gemm_core_h(g_xh + ((size_t)b * NSEQ + n0) * DIM,
                g_wqh + (size_t)d0 * DIM, smf_q, c);

    const int tid = threadIdx.x;
    const int wid = tid >> 5, lane = tid & 31;
    const int wm = wid & 3, wn = wid >> 2;
    #pragma unroll
    for (int mf = 0; mf < 2; mf++)
        #pragma unroll
        for (int nf = 0; nf < 4; nf++) {
            int dglob = d0 + wn * 32 + nf * 8 + 2 * (lane & 3);
            const int part = dglob >> 9;
            const int head = (dglob >> 6) & 7;
            const int dh = dglob & 63;
            __half* gb = (part == 0) ? g_qh : (part == 1) ? g_kh : g_vh;
            const float s = (part == 0) ? QPRE : 1.0f;
            int n = n0 + wm * 32 + mf * 16 + (lane >> 2);
            size_t idx = ((size_t)(b * HEADS + head) * NSEQ + n) * DH + dh;
            *(uint32_t*)&gb[idx] = pack2h(c[mf][nf][0] * s, c[mf][nf][1] * s);
            *(uint32_t*)&gb[idx + 8 * DH] = pack2h(c[mf][nf][2] * s, c[mf][nf][3] * s);
        }
}

// ================= Output projection (fp16) =================
__global__ __launch_bounds__(256, 3) void out_mma_kernel(const float* __restrict__ bias,
                                                         float* __restrict__ out) {
    extern __shared__ __align__(16) __half smf_o[];

    const int o0 = blockIdx.x * 64;
    const int n0 = blockIdx.y * 128;
    const int b  = blockIdx.z;

    float c[2][4][4] = {};
    gemm_core_h(g_aoh + ((size_t)b * NSEQ + n0) * DIM,
                g_woh + (size_t)o0 * DIM, smf_o, c);

    const int tid = threadIdx.x;
    const int wid = tid >> 5, lane = tid & 31;
    const int wm = wid & 3, wn = wid >> 2;
    #pragma unroll
    for (int nf = 0; nf < 4; nf++) {
        int o = o0 + wn * 32 + nf * 8 + 2 * (lane & 3);
        float b0v = __ldg(&bias[o]);
        float b1v = __ldg(&bias[o + 1]);
        #pragma unroll
        for (int mf = 0; mf < 2; mf++) {
            int n = n0 + wm * 32 + mf * 16 + (lane >> 2);
            float* p0 = out + (size_t)(b * DIM + o) * NSEQ + n;
            float* p1 = p0 + NSEQ;
            p0[0] = c[mf][nf][0] + b0v;
            p1[0] = c[mf][nf][1] + b1v;
            p0[8] = c[mf][nf][2] + b0v;
            p1[8] = c[mf][nf][3] + b1v;
        }
    }
}

// ================= prep: weight fp16 convert + Fresnel bias table =================
__global__ void prep_kernel(const float* __restrict__ wqkv,
                            const float* __restrict__ wout,
                            const float* __restrict__ wl) {
    int g = blockIdx.x * blockDim.x + threadIdx.x;
    int i = g * 4;
    if (i < 3 * DIM * DIM) {
        float4 f = *(const float4*)(wqkv + i);
        *(uint2*)&g_wqh[i] = make_uint2(pack2h(f.x, f.y), pack2h(f.z, f.w));
    }
    if (i < DIM * DIM) {
        float4 f = *(const float4*)(wout + i);
        *(uint2*)&g_woh[i] = make_uint2(pack2h(f.x, f.y), pack2h(f.z, f.w));
    }
    if (g < 95 * 95) {
        int dy = g / 95 - 47;
        int dx = g % 95 - 47;
        double dist = sqrt((double)(dy * dy + dx * dx) + 1e-8);
        double denom = fabs((double)wl[0]) * 48.0 + 1e-6;
        double phase = 6.283185307179586476925286766559 * dist / denom;
        g_bias[g] = (float)(cos(phase) * 0.1 * 1.4426950408889634074);
    }
}

// x[b][c][n] fp32 -> g_xh[b][n][c] fp16 (transpose + convert)
__global__ void split_x_kernel(const float* __restrict__ x) {
    __shared__ float t[32][33];
    const int b = blockIdx.z;
    const int n0 = blockIdx.x * 32;
    const int c0 = blockIdx.y * 32;
    const int tx = threadIdx.x, ty = threadIdx.y;
    #pragma unroll
    for (int r = ty; r < 32; r += 8)
        t[r][tx] = x[((size_t)b * DIM + c0 + r) * NSEQ + n0 + tx];
    __syncthreads();
    #pragma unroll
    for (int r = ty; r < 32; r += 8)
        g_xh[((size_t)b * NSEQ + n0 + r) * DIM + c0 + tx] = __float2half_rn(t[tx][r]);
}

// ================= Flash attention: warp m=32, q-tile 256, full KV, double-buffer =================
// L1-traffic reduction: each K/V fragment now feeds 2x the MMAs (ldsm/MMA halved).
#define KVST 72            // row stride in halves (144B -> conflict-free ldmatrix)
#define KBUF 18432         // one K (or V) buffer: 128*72*2
#define KVBUF (2 * KBUF)
#define SMA_BIAS 0         // 53-row bias window: 5040 floats -> 20160 B
#define SMA_KIDX 20160     // 2304 u16 -> 4608 B
#define SMA_KV 24768
#define SMA_TOTAL (SMA_KV + 2 * KVBUF)   // 98496 B

__global__ __launch_bounds__(256, 1) void attn_mma_kernel() {
    extern __shared__ __align__(16) char smc[];
    float* sBias = (float*)(smc + SMA_BIAS);
    uint16_t* sKidx = (uint16_t*)(smc + SMA_KIDX);

    const int tid = threadIdx.x;
    const int w = tid >> 5, lane = tid & 31;
    const int n0 = blockIdx.x * 256;
    const int h = blockIdx.y, b = blockIdx.z;
    const int gr = lane >> 2, c2 = 2 * (lane & 3);

    const __half* Kg = g_kh + (size_t)(b * HEADS + h) * NSEQ * DH;
    const __half* Vg = g_vh + (size_t)(b * HEADS + h) * NSEQ * DH;
    const uint32_t kvB = smem_u32(smc + SMA_KV);

    auto stageKV = [&](int t, int par) {
        const int k0 = t * 128;
        const int j = tid >> 1, d0 = (tid & 1) * 32;
        const __half* kr = Kg + (size_t)(k0 + j) * DH + d0;
        const __half* vr = Vg + (size_t)(k0 + j) * DH + d0;
        uint32_t sk = kvB + par * KVBUF + (j * KVST + d0) * 2;
        uint32_t sv = sk + KBUF;
        #pragma unroll
        for (int i = 0; i < 4; i++) {
            cp16(sk + 16 * i, kr + 8 * i);
            cp16(sv + 16 * i, vr + 8 * i);
        }
    };

    stageKV(0, 0); cp_commit();

    // bias window for q rows [n0, n0+255]: qy in [qyA, qyA+5]
    const int qyA = n0 / GRID48;
    const int nb = min(5040, 9025 - qyA * 95);
    for (int i = tid; i < nb; i += 256) sBias[i] = g_bias[qyA * 95 + i];
    for (int i = tid; i < NSEQ; i += 256) sKidx[i] = (uint16_t)(i + 47 * (i / GRID48));

    // ---- Q A-fragments, m=32 per warp (2 m16 frags), prescaled fp16 ----
    uint32_t qf[2][4][4];
    {
        const __half* Qg = g_qh + ((size_t)(b * HEADS + h) * NSEQ + n0 + 32 * w) * DH;
        #pragma unroll
        for (int mf = 0; mf < 2; mf++)
            #pragma unroll
            for (int kk = 0; kk < 4; kk++)
                #pragma unroll
                for (int hf = 0; hf < 2; hf++) {
                    int d = kk * 16 + hf * 8 + c2;
                    qf[mf][kk][hf * 2 + 0] =
                        *(const uint32_t*)(Qg + (size_t)(16 * mf + gr) * DH + d);
                    qf[mf][kk][hf * 2 + 1] =
                        *(const uint32_t*)(Qg + (size_t)(16 * mf + gr + 8) * DH + d);
                }
    }

    // per-thread bias row bases for the 4 q-rows
    int qb[4];
    #pragma unroll
    for (int r4 = 0; r4 < 4; r4++) {
        int qr = n0 + 32 * w + 8 * r4 + gr;
        qb[r4] = (qr / GRID48 - qyA) * 95 + (qr % GRID48) + 4512;
    }

    const int rB = (lane & 7) + ((lane >> 4) << 3);
    const int cB = ((lane >> 3) & 1) << 3;
    const int rV = lane & 15;
    const int cV = (lane >> 4) << 3;

    float o[2][8][4] = {};
    float lr[4] = {0.f, 0.f, 0.f, 0.f};

    for (int t = 0; t < NSEQ / 128; t++) {
        if (t < NSEQ / 128 - 1) {
            stageKV(t + 1, (t + 1) & 1);
            cp_commit();
            cp_wait<1>();
        } else {
            cp_wait<0>();
        }
        __syncthreads();

        const uint32_t kB = kvB + (uint32_t)((t & 1) * KVBUF);
        const uint32_t vB = kB + KBUF;
        const int k0 = t * 128;

        #pragma unroll
        for (int j = 0; j < 8; j++) {
            // ---- K fragments (reused by both m16 halves) ----
            uint32_t kb[4][4];
            #pragma unroll
            for (int kk = 0; kk < 4; kk++) {
                uint32_t off = (uint32_t)(((j * 16 + rB) * KVST + kk * 16 + cB) * 2);
                ldsm_x4(kb[kk][0], kb[kk][1], kb[kk][2], kb[kk][3], kB + off);
            }
            // ---- S = Q K^T : 4 independent accumulator chains ----
            float s[4][4] = {};
            #pragma unroll
            for (int kk = 0; kk < 4; kk++) {
                mma16816h(s[0], qf[0][kk][0], qf[0][kk][1], qf[0][kk][2], qf[0][kk][3],
                          kb[kk][0], kb[kk][1]);
                mma16816h(s[1], qf[0][kk][0], qf[0][kk][1], qf[0][kk][2], qf[0][kk][3],
                          kb[kk][2], kb[kk][3]);
                mma16816h(s[2], qf[1][kk][0], qf[1][kk][1], qf[1][kk][2], qf[1][kk][3],
                          kb[kk][0], kb[kk][1]);
                mma16816h(s[3], qf[1][kk][0], qf[1][kk][1], qf[1][kk][2], qf[1][kk][3],
                          kb[kk][2], kb[kk][3]);
            }

            // ---- V fragments issued early (latency hidden under exp phase) ----
            uint32_t vb[4][4];
            #pragma unroll
            for (int nf2 = 0; nf2 < 4; nf2++) {
                uint32_t off = (uint32_t)(((j * 16 + rV) * KVST + nf2 * 16 + cV) * 2);
                ldsm_x4t(vb[nf2][0], vb[nf2][1], vb[nf2][2], vb[nf2][3], vB + off);
            }

            // ---- bias + exp2 + pack P (2 kidx LDS serve 16 exps) ----
            int kj0 = k0 + 16 * j + c2;
            uint32_t pr0 = *(const uint32_t*)(sKidx + kj0);
            uint32_t pr1 = *(const uint32_t*)(sKidx + kj0 + 8);
            int ka0 = pr0 & 0xffff, ka1 = pr0 >> 16;
            int kb0 = pr1 & 0xffff, kb1 = pr1 >> 16;

            uint32_t pa[2][4];
            #pragma unroll
            for (int mf = 0; mf < 2; mf++) {
                int q0 = qb[2 * mf], q1 = qb[2 * mf + 1];
                float p0 = ex2(s[2 * mf][0] + sBias[q0 - ka0]);
                float p1 = ex2(s[2 * mf][1] + sBias[q0 - ka1]);
                float p2 = ex2(s[2 * mf][2] + sBias[q1 - ka0]);
                float p3 = ex2(s[2 * mf][3] + sBias[q1 - ka1]);
                float p4 = ex2(s[2 * mf + 1][0] + sBias[q0 - kb0]);
                float p5 = ex2(s[2 * mf + 1][1] + sBias[q0 - kb1]);
                float p6 = ex2(s[2 * mf + 1][2] + sBias[q1 - kb0]);
                float p7 = ex2(s[2 * mf + 1][3] + sBias[q1 - kb1]);
                lr[2 * mf]     += p0 + p1 + p4 + p5;
                lr[2 * mf + 1] += p2 + p3 + p6 + p7;
                pa[mf][0] = pack2h(p0, p1);
                pa[mf][1] = pack2h(p2, p3);
                pa[mf][2] = pack2h(p4, p5);
                pa[mf][3] = pack2h(p6, p7);
            }

            // ---- O += P V (V fragments reused by both m16 halves) ----
            #pragma unroll
            for (int nf2 = 0; nf2 < 4; nf2++) {
                mma16816h(o[0][2 * nf2],     pa[0][0], pa[0][1], pa[0][2], pa[0][3],
                          vb[nf2][0], vb[nf2][1]);
                mma16816h(o[0][2 * nf2 + 1], pa[0][0], pa[0][1], pa[0][2], pa[0][3],
                          vb[nf2][2], vb[nf2][3]);
                mma16816h(o[1][2 * nf2],     pa[1][0], pa[1][1], pa[1][2], pa[1][3],
                          vb[nf2][0], vb[nf2][1]);
                mma16816h(o[1][2 * nf2 + 1], pa[1][0], pa[1][1], pa[1][2], pa[1][3],
                          vb[nf2][2], vb[nf2][3]);
            }
        }
        __syncthreads();   // compute(t) done before stage(t+2) overwrites this buffer
    }

    // ---- normalize + write g_aoh (fp16) ----
    #pragma unroll
    for (int r4 = 0; r4 < 4; r4++) {
        lr[r4] += __shfl_xor_sync(0xffffffffu, lr[r4], 1);
        lr[r4] += __shfl_xor_sync(0xffffffffu, lr[r4], 2);
    }

    #pragma unroll
    for (int mf = 0; mf < 2; mf++) {
        float i0 = 1.0f / lr[2 * mf];
        float i1 = 1.0f / lr[2 * mf + 1];
        size_t base0 = ((size_t)b * NSEQ + n0 + 32 * w + 16 * mf + gr) * DIM + h * DH;
        size_t base1 = base0 + (size_t)8 * DIM;
        #pragma unroll
        for (int nf = 0; nf < 8; nf++) {
            *(uint32_t*)&g_aoh[base0 + 8 * nf + c2] =
                pack2h(o[mf][nf][0] * i0, o[mf][nf][1] * i0);
            *(uint32_t*)&g_aoh[base1 + 8 * nf + c2] =
                pack2h(o[mf][nf][2] * i1, o[mf][nf][3] * i1);
        }
    }
}

// ================= launch =================
extern "C" void kernel_launch(void* const* d_in, const int* in_sizes, int n_in,
                              void* d_out, int out_size) {
    const float* x     = (const float*)d_in[0];
    const float* w_qkv = (const float*)d_in[1];
    const float* w_out = (const float*)d_in[2];
    const float* b_out = (const float*)d_in[3];
    const float* wl    = (const float*)d_in[4];
    float* out = (float*)d_out;

    (void)in_sizes; (void)n_in; (void)out_size;

    cudaFuncSetAttribute(attn_mma_kernel,
                         cudaFuncAttributeMaxDynamicSharedMemorySize, SMA_TOTAL);
    cudaFuncSetAttribute(qkv_mma_kernel,
                         cudaFuncAttributeMaxDynamicSharedMemorySize, GSM_TOTAL);
    cudaFuncSetAttribute(out_mma_kernel,
                         cudaFuncAttributeMaxDynamicSharedMemorySize, GSM_TOTAL);

    split_x_kernel<<<dim3(NSEQ / 32, DIM / 32, BATCH), dim3(32, 8)>>>(x);
    prep_kernel<<<(3 * DIM * DIM / 4 + 255) / 256, 256>>>(w_qkv, w_out, wl);

    qkv_mma_kernel<<<dim3(3 * DIM / 64, NSEQ / 128, BATCH), 256, GSM_TOTAL>>>();
    attn_mma_kernel<<<dim3(NSEQ / 256, HEADS, BATCH), 256, SMA_TOTAL>>>();
    out_mma_kernel<<<dim3(DIM / 64, NSEQ / 128, BATCH), 256, GSM_TOTAL>>>(b_out, out);
}

// round 14
// speedup vs baseline: 1.2123x; 1.0947x over previous
#include <cuda_runtime.h>
#include <cuda_fp16.h>
#include <cstdint>
#include <cstdio>

#define BATCH 2
#define HEADS 8
#define DH 64
#define NSEQ 2304
#define DIM 512
#define GRID48 48
#define LOG2E 1.4426950408889634f
#define QPRE (0.125f * LOG2E)
#define BIAS_SHIFT 6.0

// ================= scratch (static device globals; no allocations) =================
__device__ __align__(256) float g_bias[95 * 95];   // cos*0.1*log2e - 6 (exp2-domain, centered)

__device__ __align__(256) __half g_xh[(size_t)BATCH * NSEQ * DIM];    // [b][n][c]
__device__ __align__(256) __half g_wqh[(size_t)3 * DIM * DIM];        // [d][c]
__device__ __align__(256) __half g_woh[(size_t)DIM * DIM];            // [o][c]
__device__ __align__(256) __half g_qh[(size_t)BATCH * HEADS * NSEQ * DH];  // prescaled
__device__ __align__(256) __half g_kh[(size_t)BATCH * HEADS * NSEQ * DH];
__device__ __align__(256) __half g_vh[(size_t)BATCH * HEADS * NSEQ * DH];
__device__ __align__(256) __half g_aoh[(size_t)BATCH * NSEQ * DIM];   // [b*n][c]

// ================= helpers =================
__device__ __forceinline__ uint32_t smem_u32(const void* p) {
    uint32_t a;
    asm("{ .reg .u64 t; cvta.to.shared.u64 t, %1; cvt.u32.u64 %0, t; }" : "=r"(a) : "l"(p));
    return a;
}
__device__ __forceinline__ void ldsm_x4(uint32_t& r0, uint32_t& r1, uint32_t& r2, uint32_t& r3,
                                        uint32_t addr) {
    asm volatile("ldmatrix.sync.aligned.m8n8.x4.shared.b16 {%0,%1,%2,%3}, [%4];"
                 : "=r"(r0), "=r"(r1), "=r"(r2), "=r"(r3) : "r"(addr));
}
__device__ __forceinline__ void ldsm_x4t(uint32_t& r0, uint32_t& r1, uint32_t& r2, uint32_t& r3,
                                         uint32_t addr) {
    asm volatile("ldmatrix.sync.aligned.m8n8.x4.trans.shared.b16 {%0,%1,%2,%3}, [%4];"
                 : "=r"(r0), "=r"(r1), "=r"(r2), "=r"(r3) : "r"(addr));
}
__device__ __forceinline__ void mma16816h(float* c, uint32_t a0, uint32_t a1, uint32_t a2,
                                          uint32_t a3, uint32_t b0, uint32_t b1) {
    asm volatile(
        "mma.sync.aligned.m16n8k16.row.col.f32.f16.f16.f32 "
        "{%0,%1,%2,%3}, {%4,%5,%6,%7}, {%8,%9}, {%0,%1,%2,%3};"
        : "+f"(c[0]), "+f"(c[1]), "+f"(c[2]), "+f"(c[3])
        : "r"(a0), "r"(a1), "r"(a2), "r"(a3), "r"(b0), "r"(b1));
}
__device__ __forceinline__ uint32_t pack2h(float x, float y) {
    uint32_t r;
    asm("cvt.rn.f16x2.f32 %0, %1, %2;" : "=r"(r) : "f"(y), "f"(x));
    return r;
}
__device__ __forceinline__ uint32_t ex2h2(uint32_t x) {
    uint32_t y;
    asm("ex2.approx.f16x2 %0, %1;" : "=r"(y) : "r"(x));
    return y;
}
__device__ __forceinline__ void cp16(uint32_t s, const void* g) {
    asm volatile("cp.async.cg.shared.global [%0], [%1], 16;" :: "r"(s), "l"(g));
}
__device__ __forceinline__ void cp_commit() {
    asm volatile("cp.async.commit_group;" ::: "memory");
}
template <int N>
__device__ __forceinline__ void cp_wait() {
    asm volatile("cp.async.wait_group %0;" :: "n"(N) : "memory");
}

// ================= dense GEMM: CTA 128(m) x 64(n), warp 32x32, 3-stage ring =================
#define TSA 40
#define A_HALVES (128 * TSA)
#define B_HALVES (64 * TSA)
#define STG_HALVES (A_HALVES + B_HALVES)
#define STG_BYTES (STG_HALVES * 2)       // 15360
#define GSM_TOTAL (3 * STG_BYTES)        // 46080

__device__ __forceinline__ void gemm_core_h(
    const __half* __restrict__ A, const __half* __restrict__ B,
    __half* smf, float c[2][4][4])
{
    const int tid = threadIdx.x;
    const int wid = tid >> 5;
    const int lane = tid & 31;
    const int wm = wid & 3, wn = wid >> 2;
    const uint32_t base = smem_u32(smf);

    uint32_t aAddr[2][2], bAddr[2][2];
    {
        int aRow = wm * 32 + (lane & 15);
        int aCol = (lane >> 4) * 8;
        #pragma unroll
        for (int mf = 0; mf < 2; mf++)
            #pragma unroll
            for (int ks = 0; ks < 2; ks++)
                aAddr[mf][ks] = base + ((aRow + mf * 16) * TSA + ks * 16 + aCol) * 2;
        int bRow = wn * 32 + (lane & 7) + ((lane >> 4) << 3);
        int bCol = ((lane >> 3) & 1) << 3;
        #pragma unroll
        for (int np = 0; np < 2; np++)
            #pragma unroll
            for (int ks = 0; ks < 2; ks++)
                bAddr[np][ks] = base + A_HALVES * 2 +
                                ((bRow + np * 16) * TSA + ks * 16 + bCol) * 2;
    }

    const int ldRow = tid >> 2;     // 0..63
    const int ldSeg = tid & 3;

    auto stage = [&](int ch, int par) {
        const int c0 = ch * 32;
        const uint32_t bb = base + par * STG_BYTES;
        cp16(bb + (ldRow * TSA + ldSeg * 8) * 2,
             A + (size_t)ldRow * DIM + c0 + ldSeg * 8);
        cp16(bb + ((ldRow + 64) * TSA + ldSeg * 8) * 2,
             A + (size_t)(ldRow + 64) * DIM + c0 + ldSeg * 8);
        cp16(bb + A_HALVES * 2 + (ldRow * TSA + ldSeg * 8) * 2,
             B + (size_t)ldRow * DIM + c0 + ldSeg * 8);
    };

    stage(0, 0); cp_commit();
    stage(1, 1); cp_commit();

    #pragma unroll
    for (int ch = 0; ch < 16; ch++) {
        if (ch < 15) cp_wait<1>(); else cp_wait<0>();
        __syncthreads();
        if (ch < 14) {
            stage(ch + 2, (ch + 2) % 3);
            cp_commit();
        }

        const uint32_t bo = (uint32_t)((ch % 3) * STG_BYTES);
        #pragma unroll
        for (int ks = 0; ks < 2; ks++) {
            uint32_t aa[2][4];
            #pragma unroll
            for (int mf = 0; mf < 2; mf++)
                ldsm_x4(aa[mf][0], aa[mf][1], aa[mf][2], aa[mf][3], aAddr[mf][ks] + bo);
            uint32_t bb[4][2];
            #pragma unroll
            for (int np = 0; np < 2; np++)
                ldsm_x4(bb[2 * np][0], bb[2 * np][1], bb[2 * np + 1][0], bb[2 * np + 1][1],
                        bAddr[np][ks] + bo);
            #pragma unroll
            for (int mf = 0; mf < 2; mf++)
                #pragma unroll
                for (int nf = 0; nf < 4; nf++)
                    mma16816h(c[mf][nf], aa[mf][0], aa[mf][1], aa[mf][2], aa[mf][3],
                              bb[nf][0], bb[nf][1]);
        }
    }
}

// ================= QKV GEMM (fp16) =================
__global__ __launch_bounds__(256, 3) void qkv_mma_kernel() {
    extern __shared__ __align__(16) __half smf_q[];

    const int d0 = blockIdx.x * 64;
    const int n0 = blockIdx.y * 128;
    const int b  = blockIdx.z;

    float c[2][4][4] = {};
    gemm_core_h(g_xh + ((size_t)b * NSEQ + n0) * DIM,
                g_wqh + (size_t)d0 * DIM, smf_q, c);

    const int tid = threadIdx.x;
    const int wid = tid >> 5, lane = tid & 31;
    const int wm = wid & 3, wn = wid >> 2;
    #pragma unroll
    for (int mf = 0; mf < 2; mf++)
        #pragma unroll
        for (int nf = 0; nf < 4; nf++) {
            int dglob = d0 + wn * 32 + nf * 8 + 2 * (lane & 3);
            const int part = dglob >> 9;
            const int head = (dglob >> 6) & 7;
            const int dh = dglob & 63;
            __half* gb = (part == 0) ? g_qh : (part == 1) ? g_kh : g_vh;
            const float s = (part == 0) ? QPRE : 1.0f;
            int n = n0 + wm * 32 + mf * 16 + (lane >> 2);
            size_t idx = ((size_t)(b * HEADS + head) * NSEQ + n) * DH + dh;
            *(uint32_t*)&gb[idx] = pack2h(c[mf][nf][0] * s, c[mf][nf][1] * s);
            *(uint32_t*)&gb[idx + 8 * DH] = pack2h(c[mf][nf][2] * s, c[mf][nf][3] * s);
        }
}

// ================= Output projection (fp16) =================
__global__ __launch_bounds__(256, 3) void out_mma_kernel(const float* __restrict__ bias,
                                                         float* __restrict__ out) {
    extern __shared__ __align__(16) __half smf_o[];

    const int o0 = blockIdx.x * 64;
    const int n0 = blockIdx.y * 128;
    const int b  = blockIdx.z;

    float c[2][4][4] = {};
    gemm_core_h(g_aoh + ((size_t)b * NSEQ + n0) * DIM,
                g_woh + (size_t)o0 * DIM, smf_o, c);

    const int tid = threadIdx.x;
    const int wid = tid >> 5, lane = tid & 31;
    const int wm = wid & 3, wn = wid >> 2;
    #pragma unroll
    for (int nf = 0; nf < 4; nf++) {
        int o = o0 + wn * 32 + nf * 8 + 2 * (lane & 3);
        float b0v = __ldg(&bias[o]);
        float b1v = __ldg(&bias[o + 1]);
        #pragma unroll
        for (int mf = 0; mf < 2; mf++) {
            int n = n0 + wm * 32 + mf * 16 + (lane >> 2);
            float* p0 = out + (size_t)(b * DIM + o) * NSEQ + n;
            float* p1 = p0 + NSEQ;
            p0[0] = c[mf][nf][0] + b0v;
            p1[0] = c[mf][nf][1] + b1v;
            p0[8] = c[mf][nf][2] + b0v;
            p1[8] = c[mf][nf][3] + b1v;
        }
    }
}

// ================= prep: weight fp16 convert + Fresnel bias table (centered) =================
__global__ void prep_kernel(const float* __restrict__ wqkv,
                            const float* __restrict__ wout,
                            const float* __restrict__ wl) {
    int g = blockIdx.x * blockDim.x + threadIdx.x;
    int i = g * 4;
    if (i < 3 * DIM * DIM) {
        float4 f = *(const float4*)(wqkv + i);
        *(uint2*)&g_wqh[i] = make_uint2(pack2h(f.x, f.y), pack2h(f.z, f.w));
    }
    if (i < DIM * DIM) {
        float4 f = *(const float4*)(wout + i);
        *(uint2*)&g_woh[i] = make_uint2(pack2h(f.x, f.y), pack2h(f.z, f.w));
    }
    if (g < 95 * 95) {
        int dy = g / 95 - 47;
        int dx = g % 95 - 47;
        double dist = sqrt((double)(dy * dy + dx * dx) + 1e-8);
        double denom = fabs((double)wl[0]) * 48.0 + 1e-6;
        double phase = 6.283185307179586476925286766559 * dist / denom;
        // exp2-domain bias, centered by -6: p and lr scale by 2^-6, ratio invariant
        g_bias[g] = (float)(cos(phase) * 0.1 * 1.4426950408889634074 - BIAS_SHIFT);
    }
}

// x[b][c][n] fp32 -> g_xh[b][n][c] fp16 (transpose + convert)
__global__ void split_x_kernel(const float* __restrict__ x) {
    __shared__ float t[32][33];
    const int b = blockIdx.z;
    const int n0 = blockIdx.x * 32;
    const int c0 = blockIdx.y * 32;
    const int tx = threadIdx.x, ty = threadIdx.y;
    #pragma unroll
    for (int r = ty; r < 32; r += 8)
        t[r][tx] = x[((size_t)b * DIM + c0 + r) * NSEQ + n0 + tx];
    __syncthreads();
    #pragma unroll
    for (int r = ty; r < 32; r += 8)
        g_xh[((size_t)b * NSEQ + n0 + r) * DIM + c0 + tx] = __float2half_rn(t[tx][r]);
}

// ================= Flash attention: warp m=32, packed f16x2 exp, lr via ones-MMA =================
#define KVST 72            // row stride in halves (144B -> conflict-free ldmatrix)
#define KBUF 18432         // one K (or V) buffer: 128*72*2
#define KVBUF (2 * KBUF)
#define SMA_BIAS 0         // 53-row bias window: 5040 floats -> 20160 B
#define SMA_KIDX 20160     // 2304 u16 -> 4608 B
#define SMA_KV 24768
#define SMA_TOTAL (SMA_KV + 2 * KVBUF + 32)   // +32 pad: nf2=4 trans-ldsm overread guard

__global__ __launch_bounds__(256, 1) void attn_mma_kernel() {
    extern __shared__ __align__(16) char smc[];
    float* sBias = (float*)(smc + SMA_BIAS);
    uint16_t* sKidx = (uint16_t*)(smc + SMA_KIDX);

    const int tid = threadIdx.x;
    const int w = tid >> 5, lane = tid & 31;
    const int n0 = blockIdx.x * 256;
    const int h = blockIdx.y, b = blockIdx.z;
    const int gr = lane >> 2, c2 = 2 * (lane & 3);

    const __half* Kg = g_kh + (size_t)(b * HEADS + h) * NSEQ * DH;
    const __half* Vg = g_vh + (size_t)(b * HEADS + h) * NSEQ * DH;
    const uint32_t kvB = smem_u32(smc + SMA_KV);

    auto stageKV = [&](int t, int par) {
        const int k0 = t * 128;
        const int j = tid >> 1, d0 = (tid & 1) * 32;
        const __half* kr = Kg + (size_t)(k0 + j) * DH + d0;
        const __half* vr = Vg + (size_t)(k0 + j) * DH + d0;
        uint32_t sk = kvB + par * KVBUF + (j * KVST + d0) * 2;
        uint32_t sv = sk + KBUF;
        #pragma unroll
        for (int i = 0; i < 4; i++) {
            cp16(sk + 16 * i, kr + 8 * i);
            cp16(sv + 16 * i, vr + 8 * i);
        }
        // ones column at dh=64 of V (for lr row-sum MMA); odd thread of each row pair writes
        if (tid & 1)
            *(__half*)(smc + SMA_KV + par * KVBUF + KBUF + (j * KVST + 64) * 2) =
                __float2half_rn(1.0f);
    };

    stageKV(0, 0); cp_commit();

    // bias window for q rows [n0, n0+255]: qy in [qyA, qyA+5]
    const int qyA = n0 / GRID48;
    const int nb = min(5040, 9025 - qyA * 95);
    for (int i = tid; i < nb; i += 256) sBias[i] = g_bias[qyA * 95 + i];
    for (int i = tid; i < NSEQ; i += 256) sKidx[i] = (uint16_t)(i + 47 * (i / GRID48));

    // ---- Q A-fragments, m=32 per warp (2 m16 frags), prescaled fp16 ----
    uint32_t qf[2][4][4];
    {
        const __half* Qg = g_qh + ((size_t)(b * HEADS + h) * NSEQ + n0 + 32 * w) * DH;
        #pragma unroll
        for (int mf = 0; mf < 2; mf++)
            #pragma unroll
            for (int kk = 0; kk < 4; kk++)
                #pragma unroll
                for (int hf = 0; hf < 2; hf++) {
                    int d = kk * 16 + hf * 8 + c2;
                    qf[mf][kk][hf * 2 + 0] =
                        *(const uint32_t*)(Qg + (size_t)(16 * mf + gr) * DH + d);
                    qf[mf][kk][hf * 2 + 1] =
                        *(const uint32_t*)(Qg + (size_t)(16 * mf + gr + 8) * DH + d);
                }
    }

    int qb[4];
    #pragma unroll
    for (int r4 = 0; r4 < 4; r4++) {
        int qr = n0 + 32 * w + 8 * r4 + gr;
        qb[r4] = (qr / GRID48 - qyA) * 95 + (qr % GRID48) + 4512;
    }

    const int rB = (lane & 7) + ((lane >> 4) << 3);
    const int cB = ((lane >> 3) & 1) << 3;
    const int rV = lane & 15;
    const int cV = (lane >> 4) << 3;

    float o[2][8][4] = {};
    float oe[2][4] = {};     // ones-column accumulators: col 64 = row sums (lr)

    for (int t = 0; t < NSEQ / 128; t++) {
        if (t < NSEQ / 128 - 1) {
            stageKV(t + 1, (t + 1) & 1);
            cp_commit();
            cp_wait<1>();
        } else {
            cp_wait<0>();
        }
        __syncthreads();

        const uint32_t kB = kvB + (uint32_t)((t & 1) * KVBUF);
        const uint32_t vB = kB + KBUF;
        const int k0 = t * 128;

        #pragma unroll
        for (int j = 0; j < 8; j++) {
            // ---- K fragments (reused by both m16 halves) ----
            uint32_t kb[4][4];
            #pragma unroll
            for (int kk = 0; kk < 4; kk++) {
                uint32_t off = (uint32_t)(((j * 16 + rB) * KVST + kk * 16 + cB) * 2);
                ldsm_x4(kb[kk][0], kb[kk][1], kb[kk][2], kb[kk][3], kB + off);
            }
            // ---- S = Q K^T : 4 independent accumulator chains ----
            float s[4][4] = {};
            #pragma unroll
            for (int kk = 0; kk < 4; kk++) {
                mma16816h(s[0], qf[0][kk][0], qf[0][kk][1], qf[0][kk][2], qf[0][kk][3],
                          kb[kk][0], kb[kk][1]);
                mma16816h(s[1], qf[0][kk][0], qf[0][kk][1], qf[0][kk][2], qf[0][kk][3],
                          kb[kk][2], kb[kk][3]);
                mma16816h(s[2], qf[1][kk][0], qf[1][kk][1], qf[1][kk][2], qf[1][kk][3],
                          kb[kk][0], kb[kk][1]);
                mma16816h(s[3], qf[1][kk][0], qf[1][kk][1], qf[1][kk][2], qf[1][kk][3],
                          kb[kk][2], kb[kk][3]);
            }

            // ---- V fragments issued early (latency hidden under exp phase) ----
            uint32_t vb[4][4];
            #pragma unroll
            for (int nf2 = 0; nf2 < 4; nf2++) {
                uint32_t off = (uint32_t)(((j * 16 + rV) * KVST + nf2 * 16 + cV) * 2);
                ldsm_x4t(vb[nf2][0], vb[nf2][1], vb[nf2][2], vb[nf2][3], vB + off);
            }
            // ones-column fragment (output cols 64-71; only col 64 meaningful)
            uint32_t ob0, ob1, ob2, ob3;
            {
                uint32_t off = (uint32_t)(((j * 16 + rV) * KVST + 64 + cV) * 2);
                ldsm_x4t(ob0, ob1, ob2, ob3, vB + off);
            }

            // ---- bias add (fp32) -> pack f16x2 -> packed exp2 ----
            int kj0 = k0 + 16 * j + c2;
            uint32_t pr0 = *(const uint32_t*)(sKidx + kj0);
            uint32_t pr1 = *(const uint32_t*)(sKidx + kj0 + 8);
            int ka0 = pr0 & 0xffff, ka1 = pr0 >> 16;
            int kb0 = pr1 & 0xffff, kb1 = pr1 >> 16;

            uint32_t pa[2][4];
            #pragma unroll
            for (int mf = 0; mf < 2; mf++) {
                int q0 = qb[2 * mf], q1 = qb[2 * mf + 1];
                pa[mf][0] = ex2h2(pack2h(s[2 * mf][0] + sBias[q0 - ka0],
                                         s[2 * mf][1] + sBias[q0 - ka1]));
                pa[mf][1] = ex2h2(pack2h(s[2 * mf][2] + sBias[q1 - ka0],
                                         s[2 * mf][3] + sBias[q1 - ka1]));
                pa[mf][2] = ex2h2(pack2h(s[2 * mf + 1][0] + sBias[q0 - kb0],
                                         s[2 * mf + 1][1] + sBias[q0 - kb1]));
                pa[mf][3] = ex2h2(pack2h(s[2 * mf + 1][2] + sBias[q1 - kb0],
                                         s[2 * mf + 1][3] + sBias[q1 - kb1]));
            }

            // ---- O += P V (V fragments reused by both m16 halves) ----
            #pragma unroll
            for (int nf2 = 0; nf2 < 4; nf2++) {
                mma16816h(o[0][2 * nf2],     pa[0][0], pa[0][1], pa[0][2], pa[0][3],
                          vb[nf2][0], vb[nf2][1]);
                mma16816h(o[0][2 * nf2 + 1], pa[0][0], pa[0][1], pa[0][2], pa[0][3],
                          vb[nf2][2], vb[nf2][3]);
                mma16816h(o[1][2 * nf2],     pa[1][0], pa[1][1], pa[1][2], pa[1][3],
                          vb[nf2][0], vb[nf2][1]);
                mma16816h(o[1][2 * nf2 + 1], pa[1][0], pa[1][1], pa[1][2], pa[1][3],
                          vb[nf2][2], vb[nf2][3]);
            }
            // lr row sums via ones column
            mma16816h(oe[0], pa[0][0], pa[0][1], pa[0][2], pa[0][3], ob0, ob1);
            mma16816h(oe[1], pa[1][0], pa[1][1], pa[1][2], pa[1][3], ob0, ob1);
        }
        __syncthreads();   // compute(t) done before stage(t+2) overwrites this buffer
    }

    // ---- lr lives in col 64 = lanes with (lane&3)==0, regs oe[mf][0]/oe[mf][2] ----
    #pragma unroll
    for (int mf = 0; mf < 2; mf++) {
        float l0 = __shfl_sync(0xffffffffu, oe[mf][0], lane & 28);
        float l1 = __shfl_sync(0xffffffffu, oe[mf][2], lane & 28);
        float i0 = 1.0f / l0;
        float i1 = 1.0f / l1;
        size_t base0 = ((size_t)b * NSEQ + n0 + 32 * w + 16 * mf + gr) * DIM + h * DH;
        size_t base1 = base0 + (size_t)8 * DIM;
        #pragma unroll
        for (int nf = 0; nf < 8; nf++) {
            *(uint32_t*)&g_aoh[base0 + 8 * nf + c2] =
                pack2h(o[mf][nf][0] * i0, o[mf][nf][1] * i0);
            *(uint32_t*)&g_aoh[base1 + 8 * nf + c2] =
                pack2h(o[mf][nf][2] * i1, o[mf][nf][3] * i1);
        }
    }
}

// ================= launch =================
extern "C" void kernel_launch(void* const* d_in, const int* in_sizes, int n_in,
                              void* d_out, int out_size) {
    const float* x     = (const float*)d_in[0];
    const float* w_qkv = (const float*)d_in[1];
    const float* w_out = (const float*)d_in[2];
    const float* b_out = (const float*)d_in[3];
    const float* wl    = (const float*)d_in[4];
    float* out = (float*)d_out;

    (void)in_sizes; (void)n_in; (void)out_size;

    cudaFuncSetAttribute(attn_mma_kernel,
                         cudaFuncAttributeMaxDynamicSharedMemorySize, SMA_TOTAL);
    cudaFuncSetAttribute(qkv_mma_kernel,
                         cudaFuncAttributeMaxDynamicSharedMemorySize, GSM_TOTAL);
    cudaFuncSetAttribute(out_mma_kernel,
                         cudaFuncAttributeMaxDynamicSharedMemorySize, GSM_TOTAL);

    split_x_kernel<<<dim3(NSEQ / 32, DIM / 32, BATCH), dim3(32, 8)>>>(x);
    prep_kernel<<<(3 * DIM * DIM / 4 + 255) / 256, 256>>>(w_qkv, w_out, wl);

    qkv_mma_kernel<<<dim3(3 * DIM / 64, NSEQ / 128, BATCH), 256, GSM_TOTAL>>>();
    attn_mma_kernel<<<dim3(NSEQ / 256, HEADS, BATCH), 256, SMA_TOTAL>>>();
    out_mma_kernel<<<dim3(DIM / 64, NSEQ / 128, BATCH), 256, GSM_TOTAL>>>(b_out, out);
}

// round 15
// speedup vs baseline: 1.2151x; 1.0023x over previous
#include <cuda_runtime.h>
#include <cuda_fp16.h>
#include <cstdint>
#include <cstdio>

#define BATCH 2
#define HEADS 8
#define DH 64
#define NSEQ 2304
#define DIM 512
#define GRID48 48
#define LOG2E 1.4426950408889634f
#define QPRE (0.125f * LOG2E)
#define BIAS_SHIFT 6.0

// ================= scratch (static device globals; no allocations) =================
__device__ __align__(256) float g_bias[95 * 95];   // cos*0.1*log2e - 6 (exp2-domain, centered)

__device__ __align__(256) __half g_xh[(size_t)BATCH * NSEQ * DIM];    // [b][n][c]
__device__ __align__(256) __half g_wqh[(size_t)3 * DIM * DIM];        // [d][c]
__device__ __align__(256) __half g_woh[(size_t)DIM * DIM];            // [o][c]
__device__ __align__(256) __half g_qh[(size_t)BATCH * HEADS * NSEQ * DH];  // prescaled
__device__ __align__(256) __half g_kh[(size_t)BATCH * HEADS * NSEQ * DH];
__device__ __align__(256) __half g_vh[(size_t)BATCH * HEADS * NSEQ * DH];
__device__ __align__(256) __half g_aoh[(size_t)BATCH * NSEQ * DIM];   // [b*n][c]

// ================= helpers =================
__device__ __forceinline__ uint32_t smem_u32(const void* p) {
    uint32_t a;
    asm("{ .reg .u64 t; cvta.to.shared.u64 t, %1; cvt.u32.u64 %0, t; }" : "=r"(a) : "l"(p));
    return a;
}
__device__ __forceinline__ void ldsm_x4(uint32_t& r0, uint32_t& r1, uint32_t& r2, uint32_t& r3,
                                        uint32_t addr) {
    asm volatile("ldmatrix.sync.aligned.m8n8.x4.shared.b16 {%0,%1,%2,%3}, [%4];"
                 : "=r"(r0), "=r"(r1), "=r"(r2), "=r"(r3) : "r"(addr));
}
__device__ __forceinline__ void ldsm_x4t(uint32_t& r0, uint32_t& r1, uint32_t& r2, uint32_t& r3,
                                         uint32_t addr) {
    asm volatile("ldmatrix.sync.aligned.m8n8.x4.trans.shared.b16 {%0,%1,%2,%3}, [%4];"
                 : "=r"(r0), "=r"(r1), "=r"(r2), "=r"(r3) : "r"(addr));
}
__device__ __forceinline__ void mma16816h(float* c, uint32_t a0, uint32_t a1, uint32_t a2,
                                          uint32_t a3, uint32_t b0, uint32_t b1) {
    asm volatile(
        "mma.sync.aligned.m16n8k16.row.col.f32.f16.f16.f32 "
        "{%0,%1,%2,%3}, {%4,%5,%6,%7}, {%8,%9}, {%0,%1,%2,%3};"
        : "+f"(c[0]), "+f"(c[1]), "+f"(c[2]), "+f"(c[3])
        : "r"(a0), "r"(a1), "r"(a2), "r"(a3), "r"(b0), "r"(b1));
}
__device__ __forceinline__ uint32_t pack2h(float x, float y) {
    uint32_t r;
    asm("cvt.rn.f16x2.f32 %0, %1, %2;" : "=r"(r) : "f"(y), "f"(x));
    return r;
}
__device__ __forceinline__ uint32_t ex2h2(uint32_t x) {
    uint32_t y;
    asm("ex2.approx.f16x2 %0, %1;" : "=r"(y) : "r"(x));
    return y;
}
__device__ __forceinline__ void cp16(uint32_t s, const void* g) {
    asm volatile("cp.async.cg.shared.global [%0], [%1], 16;" :: "r"(s), "l"(g));
}
__device__ __forceinline__ void cp_commit() {
    asm volatile("cp.async.commit_group;" ::: "memory");
}
template <int N>
__device__ __forceinline__ void cp_wait() {
    asm volatile("cp.async.wait_group %0;" :: "n"(N) : "memory");
}

// ================= dense GEMM: CTA 128(m) x 64(n), warp 32x32, 3-stage ring =================
#define TSA 40
#define A_HALVES (128 * TSA)
#define B_HALVES (64 * TSA)
#define STG_HALVES (A_HALVES + B_HALVES)
#define STG_BYTES (STG_HALVES * 2)       // 15360
#define GSM_TOTAL (3 * STG_BYTES)        // 46080

__device__ __forceinline__ void gemm_core_h(
    const __half* __restrict__ A, const __half* __restrict__ B,
    __half* smf, float c[2][4][4])
{
    const int tid = threadIdx.x;
    const int wid = tid >> 5;
    const int lane = tid & 31;
    const int wm = wid & 3, wn = wid >> 2;
    const uint32_t base = smem_u32(smf);

    uint32_t aAddr[2][2], bAddr[2][2];
    {
        int aRow = wm * 32 + (lane & 15);
        int aCol = (lane >> 4) * 8;
        #pragma unroll
        for (int mf = 0; mf < 2; mf++)
            #pragma unroll
            for (int ks = 0; ks < 2; ks++)
                aAddr[mf][ks] = base + ((aRow + mf * 16) * TSA + ks * 16 + aCol) * 2;
        int bRow = wn * 32 + (lane & 7) + ((lane >> 4) << 3);
        int bCol = ((lane >> 3) & 1) << 3;
        #pragma unroll
        for (int np = 0; np < 2; np++)
            #pragma unroll
            for (int ks = 0; ks < 2; ks++)
                bAddr[np][ks] = base + A_HALVES * 2 +
                                ((bRow + np * 16) * TSA + ks * 16 + bCol) * 2;
    }

    const int ldRow = tid >> 2;     // 0..63
    const int ldSeg = tid & 3;

    auto stage = [&](int ch, int par) {
        const int c0 = ch * 32;
        const uint32_t bb = base + par * STG_BYTES;
        cp16(bb + (ldRow * TSA + ldSeg * 8) * 2,
             A + (size_t)ldRow * DIM + c0 + ldSeg * 8);
        cp16(bb + ((ldRow + 64) * TSA + ldSeg * 8) * 2,
             A + (size_t)(ldRow + 64) * DIM + c0 + ldSeg * 8);
        cp16(bb + A_HALVES * 2 + (ldRow * TSA + ldSeg * 8) * 2,
             B + (size_t)ldRow * DIM + c0 + ldSeg * 8);
    };

    stage(0, 0); cp_commit();
    stage(1, 1); cp_commit();

    #pragma unroll
    for (int ch = 0; ch < 16; ch++) {
        if (ch < 15) cp_wait<1>(); else cp_wait<0>();
        __syncthreads();
        if (ch < 14) {
            stage(ch + 2, (ch + 2) % 3);
            cp_commit();
        }

        const uint32_t bo = (uint32_t)((ch % 3) * STG_BYTES);
        #pragma unroll
        for (int ks = 0; ks < 2; ks++) {
            uint32_t aa[2][4];
            #pragma unroll
            for (int mf = 0; mf < 2; mf++)
                ldsm_x4(aa[mf][0], aa[mf][1], aa[mf][2], aa[mf][3], aAddr[mf][ks] + bo);
            uint32_t bb[4][2];
            #pragma unroll
            for (int np = 0; np < 2; np++)
                ldsm_x4(bb[2 * np][0], bb[2 * np][1], bb[2 * np + 1][0], bb[2 * np + 1][1],
                        bAddr[np][ks] + bo);
            #pragma unroll
            for (int mf = 0; mf < 2; mf++)
                #pragma unroll
                for (int nf = 0; nf < 4; nf++)
                    mma16816h(c[mf][nf], aa[mf][0], aa[mf][1], aa[mf][2], aa[mf][3],
                              bb[nf][0], bb[nf][1]);
        }
    }
}

// ================= QKV GEMM (fp16) =================
__global__ __launch_bounds__(256, 3) void qkv_mma_kernel() {
    extern __shared__ __align__(16) __half smf_q[];

    const int d0 = blockIdx.x * 64;
    const int n0 = blockIdx.y * 128;
    const int b  = blockIdx.z;

    float c[2][4][4] = {};
    gemm_core_h(g_xh + ((size_t)b * NSEQ + n0) * DIM,
                g_wqh + (size_t)d0 * DIM, smf_q, c);

    const int tid = threadIdx.x;
    const int wid = tid >> 5, lane = tid & 31;
    const int wm = wid & 3, wn = wid >> 2;
    #pragma unroll
    for (int mf = 0; mf < 2; mf++)
        #pragma unroll
        for (int nf = 0; nf < 4; nf++) {
            int dglob = d0 + wn * 32 + nf * 8 + 2 * (lane & 3);
            const int part = dglob >> 9;
            const int head = (dglob >> 6) & 7;
            const int dh = dglob & 63;
            __half* gb = (part == 0) ? g_qh : (part == 1) ? g_kh : g_vh;
            const float s = (part == 0) ? QPRE : 1.0f;
            int n = n0 + wm * 32 + mf * 16 + (lane >> 2);
            size_t idx = ((size_t)(b * HEADS + head) * NSEQ + n) * DH + dh;
            *(uint32_t*)&gb[idx] = pack2h(c[mf][nf][0] * s, c[mf][nf][1] * s);
            *(uint32_t*)&gb[idx + 8 * DH] = pack2h(c[mf][nf][2] * s, c[mf][nf][3] * s);
        }
}

// ================= Output projection (fp16) =================
__global__ __launch_bounds__(256, 3) void out_mma_kernel(const float* __restrict__ bias,
                                                         float* __restrict__ out) {
    extern __shared__ __align__(16) __half smf_o[];

    const int o0 = blockIdx.x * 64;
    const int n0 = blockIdx.y * 128;
    const int b  = blockIdx.z;

    float c[2][4][4] = {};
    gemm_core_h(g_aoh + ((size_t)b * NSEQ + n0) * DIM,
                g_woh + (size_t)o0 * DIM, smf_o, c);

    const int tid = threadIdx.x;
    const int wid = tid >> 5, lane = tid & 31;
    const int wm = wid & 3, wn = wid >> 2;
    #pragma unroll
    for (int nf = 0; nf < 4; nf++) {
        int o = o0 + wn * 32 + nf * 8 + 2 * (lane & 3);
        float b0v = __ldg(&bias[o]);
        float b1v = __ldg(&bias[o + 1]);
        #pragma unroll
        for (int mf = 0; mf < 2; mf++) {
            int n = n0 + wm * 32 + mf * 16 + (lane >> 2);
            float* p0 = out + (size_t)(b * DIM + o) * NSEQ + n;
            float* p1 = p0 + NSEQ;
            p0[0] = c[mf][nf][0] + b0v;
            p1[0] = c[mf][nf][1] + b1v;
            p0[8] = c[mf][nf][2] + b0v;
            p1[8] = c[mf][nf][3] + b1v;
        }
    }
}

// ================= prep: weight fp16 convert + Fresnel bias table (centered) =================
__global__ void prep_kernel(const float* __restrict__ wqkv,
                            const float* __restrict__ wout,
                            const float* __restrict__ wl) {
    int g = blockIdx.x * blockDim.x + threadIdx.x;
    int i = g * 4;
    if (i < 3 * DIM * DIM) {
        float4 f = *(const float4*)(wqkv + i);
        *(uint2*)&g_wqh[i] = make_uint2(pack2h(f.x, f.y), pack2h(f.z, f.w));
    }
    if (i < DIM * DIM) {
        float4 f = *(const float4*)(wout + i);
        *(uint2*)&g_woh[i] = make_uint2(pack2h(f.x, f.y), pack2h(f.z, f.w));
    }
    if (g < 95 * 95) {
        int dy = g / 95 - 47;
        int dx = g % 95 - 47;
        double dist = sqrt((double)(dy * dy + dx * dx) + 1e-8);
        double denom = fabs((double)wl[0]) * 48.0 + 1e-6;
        double phase = 6.283185307179586476925286766559 * dist / denom;
        g_bias[g] = (float)(cos(phase) * 0.1 * 1.4426950408889634074 - BIAS_SHIFT);
    }
}

// x[b][c][n] fp32 -> g_xh[b][n][c] fp16 (transpose + convert)
__global__ void split_x_kernel(const float* __restrict__ x) {
    __shared__ float t[32][33];
    const int b = blockIdx.z;
    const int n0 = blockIdx.x * 32;
    const int c0 = blockIdx.y * 32;
    const int tx = threadIdx.x, ty = threadIdx.y;
    #pragma unroll
    for (int r = ty; r < 32; r += 8)
        t[r][tx] = x[((size_t)b * DIM + c0 + r) * NSEQ + n0 + tx];
    __syncthreads();
    #pragma unroll
    for (int r = ty; r < 32; r += 8)
        g_xh[((size_t)b * NSEQ + n0 + r) * DIM + c0 + tx] = __float2half_rn(t[tx][r]);
}

// ================= Flash attention: warp m=32, packed exp, constant ones-fragment =================
#define KVST 72            // row stride in halves (144B -> conflict-free ldmatrix)
#define KBUF 18432         // one K (or V) buffer: 128*72*2
#define KVBUF (2 * KBUF)
#define SMA_BIAS 0         // 53-row bias window: 5040 floats -> 20160 B
#define SMA_KIDX 20160     // 2304 u16 -> 4608 B
#define SMA_KV 24768
#define SMA_TOTAL (SMA_KV + 2 * KVBUF)

__global__ __launch_bounds__(256, 1) void attn_mma_kernel() {
    extern __shared__ __align__(16) char smc[];
    float* sBias = (float*)(smc + SMA_BIAS);
    uint16_t* sKidx = (uint16_t*)(smc + SMA_KIDX);

    const int tid = threadIdx.x;
    const int w = tid >> 5, lane = tid & 31;
    const int n0 = blockIdx.x * 256;
    const int h = blockIdx.y, b = blockIdx.z;
    const int gr = lane >> 2, c2 = 2 * (lane & 3);

    const __half* Kg = g_kh + (size_t)(b * HEADS + h) * NSEQ * DH;
    const __half* Vg = g_vh + (size_t)(b * HEADS + h) * NSEQ * DH;
    const uint32_t kvB = smem_u32(smc + SMA_KV);

    // constant B-fragment of an all-ones column at n=0 (m16n8k16): lanes 0-3 hold (1,1)
    const uint32_t onesb = (lane < 4) ? 0x3C003C00u : 0u;

    auto stageKV = [&](int t, int par) {
        const int k0 = t * 128;
        const int j = tid >> 1, d0 = (tid & 1) * 32;
        const __half* kr = Kg + (size_t)(k0 + j) * DH + d0;
        const __half* vr = Vg + (size_t)(k0 + j) * DH + d0;
        uint32_t sk = kvB + par * KVBUF + (j * KVST + d0) * 2;
        uint32_t sv = sk + KBUF;
        #pragma unroll
        for (int i = 0; i < 4; i++) {
            cp16(sk + 16 * i, kr + 8 * i);
            cp16(sv + 16 * i, vr + 8 * i);
        }
    };

    stageKV(0, 0); cp_commit();

    // bias window for q rows [n0, n0+255]: qy in [qyA, qyA+5]
    const int qyA = n0 / GRID48;
    const int nb = min(5040, 9025 - qyA * 95);
    for (int i = tid; i < nb; i += 256) sBias[i] = g_bias[qyA * 95 + i];
    for (int i = tid; i < NSEQ; i += 256) sKidx[i] = (uint16_t)(i + 47 * (i / GRID48));

    // ---- Q A-fragments, m=32 per warp (2 m16 frags), prescaled fp16 ----
    uint32_t qf[2][4][4];
    {
        const __half* Qg = g_qh + ((size_t)(b * HEADS + h) * NSEQ + n0 + 32 * w) * DH;
        #pragma unroll
        for (int mf = 0; mf < 2; mf++)
            #pragma unroll
            for (int kk = 0; kk < 4; kk++)
                #pragma unroll
                for (int hf = 0; hf < 2; hf++) {
                    int d = kk * 16 + hf * 8 + c2;
                    qf[mf][kk][hf * 2 + 0] =
                        *(const uint32_t*)(Qg + (size_t)(16 * mf + gr) * DH + d);
                    qf[mf][kk][hf * 2 + 1] =
                        *(const uint32_t*)(Qg + (size_t)(16 * mf + gr + 8) * DH + d);
                }
    }

    int qb[4];
    #pragma unroll
    for (int r4 = 0; r4 < 4; r4++) {
        int qr = n0 + 32 * w + 8 * r4 + gr;
        qb[r4] = (qr / GRID48 - qyA) * 95 + (qr % GRID48) + 4512;
    }

    const int rB = (lane & 7) + ((lane >> 4) << 3);
    const int cB = ((lane >> 3) & 1) << 3;
    const int rV = lane & 15;
    const int cV = (lane >> 4) << 3;

    float o[2][8][4] = {};
    float oe[2][4] = {};     // ones-column accumulators: element 0/2 = row sums (lr)

    for (int t = 0; t < NSEQ / 128; t++) {
        if (t < NSEQ / 128 - 1) {
            stageKV(t + 1, (t + 1) & 1);
            cp_commit();
            cp_wait<1>();
        } else {
            cp_wait<0>();
        }
        __syncthreads();

        const uint32_t kB = kvB + (uint32_t)((t & 1) * KVBUF);
        const uint32_t vB = kB + KBUF;
        const int k0 = t * 128;

        #pragma unroll 2
        for (int j = 0; j < 8; j++) {
            // ---- K fragments (reused by both m16 halves) ----
            uint32_t kb[4][4];
            #pragma unroll
            for (int kk = 0; kk < 4; kk++) {
                uint32_t off = (uint32_t)(((j * 16 + rB) * KVST + kk * 16 + cB) * 2);
                ldsm_x4(kb[kk][0], kb[kk][1], kb[kk][2], kb[kk][3], kB + off);
            }
            // ---- S = Q K^T : 4 independent accumulator chains ----
            float s[4][4] = {};
            #pragma unroll
            for (int kk = 0; kk < 4; kk++) {
                mma16816h(s[0], qf[0][kk][0], qf[0][kk][1], qf[0][kk][2], qf[0][kk][3],
                          kb[kk][0], kb[kk][1]);
                mma16816h(s[1], qf[0][kk][0], qf[0][kk][1], qf[0][kk][2], qf[0][kk][3],
                          kb[kk][2], kb[kk][3]);
                mma16816h(s[2], qf[1][kk][0], qf[1][kk][1], qf[1][kk][2], qf[1][kk][3],
                          kb[kk][0], kb[kk][1]);
                mma16816h(s[3], qf[1][kk][0], qf[1][kk][1], qf[1][kk][2], qf[1][kk][3],
                          kb[kk][2], kb[kk][3]);
            }

            // ---- V fragments issued early (latency hidden under exp phase) ----
            uint32_t vb[4][4];
            #pragma unroll
            for (int nf2 = 0; nf2 < 4; nf2++) {
                uint32_t off = (uint32_t)(((j * 16 + rV) * KVST + nf2 * 16 + cV) * 2);
                ldsm_x4t(vb[nf2][0], vb[nf2][1], vb[nf2][2], vb[nf2][3], vB + off);
            }

            // ---- bias add (fp32) -> pack f16x2 -> packed exp2 ----
            int kj0 = k0 + 16 * j + c2;
            uint32_t pr0 = *(const uint32_t*)(sKidx + kj0);
            uint32_t pr1 = *(const uint32_t*)(sKidx + kj0 + 8);
            int ka0 = pr0 & 0xffff, ka1 = pr0 >> 16;
            int kb0 = pr1 & 0xffff, kb1 = pr1 >> 16;

            uint32_t pa[2][4];
            #pragma unroll
            for (int mf = 0; mf < 2; mf++) {
                int q0 = qb[2 * mf], q1 = qb[2 * mf + 1];
                pa[mf][0] = ex2h2(pack2h(s[2 * mf][0] + sBias[q0 - ka0],
                                         s[2 * mf][1] + sBias[q0 - ka1]));
                pa[mf][1] = ex2h2(pack2h(s[2 * mf][2] + sBias[q1 - ka0],
                                         s[2 * mf][3] + sBias[q1 - ka1]));
                pa[mf][2] = ex2h2(pack2h(s[2 * mf + 1][0] + sBias[q0 - kb0],
                                         s[2 * mf + 1][1] + sBias[q0 - kb1]));
                pa[mf][3] = ex2h2(pack2h(s[2 * mf + 1][2] + sBias[q1 - kb0],
                                         s[2 * mf + 1][3] + sBias[q1 - kb1]));
            }

            // ---- O += P V (V fragments reused by both m16 halves) ----
            #pragma unroll
            for (int nf2 = 0; nf2 < 4; nf2++) {
                mma16816h(o[0][2 * nf2],     pa[0][0], pa[0][1], pa[0][2], pa[0][3],
                          vb[nf2][0], vb[nf2][1]);
                mma16816h(o[0][2 * nf2 + 1], pa[0][0], pa[0][1], pa[0][2], pa[0][3],
                          vb[nf2][2], vb[nf2][3]);
                mma16816h(o[1][2 * nf2],     pa[1][0], pa[1][1], pa[1][2], pa[1][3],
                          vb[nf2][0], vb[nf2][1]);
                mma16816h(o[1][2 * nf2 + 1], pa[1][0], pa[1][1], pa[1][2], pa[1][3],
                          vb[nf2][2], vb[nf2][3]);
            }
            // lr row sums via constant ones-fragment
            mma16816h(oe[0], pa[0][0], pa[0][1], pa[0][2], pa[0][3], onesb, onesb);
            mma16816h(oe[1], pa[1][0], pa[1][1], pa[1][2], pa[1][3], onesb, onesb);
        }
        __syncthreads();   // compute(t) done before stage(t+2) overwrites this buffer
    }

    // ---- lr lives in output col 0 of oe: lanes with (lane&3)==0, regs oe[mf][0]/oe[mf][2] ----
    #pragma unroll
    for (int mf = 0; mf < 2; mf++) {
        float l0 = __shfl_sync(0xffffffffu, oe[mf][0], lane & 28);
        float l1 = __shfl_sync(0xffffffffu, oe[mf][2], lane & 28);
        float i0 = 1.0f / l0;
        float i1 = 1.0f / l1;
        size_t base0 = ((size_t)b * NSEQ + n0 + 32 * w + 16 * mf + gr) * DIM + h * DH;
        size_t base1 = base0 + (size_t)8 * DIM;
        #pragma unroll
        for (int nf = 0; nf < 8; nf++) {
            *(uint32_t*)&g_aoh[base0 + 8 * nf + c2] =
                pack2h(o[mf][nf][0] * i0, o[mf][nf][1] * i0);
            *(uint32_t*)&g_aoh[base1 + 8 * nf + c2] =
                pack2h(o[mf][nf][2] * i1, o[mf][nf][3] * i1);
        }
    }
}

// ================= launch =================
extern "C" void kernel_launch(void* const* d_in, const int* in_sizes, int n_in,
                              void* d_out, int out_size) {
    const float* x     = (const float*)d_in[0];
    const float* w_qkv = (const float*)d_in[1];
    const float* w_out = (const float*)d_in[2];
    const float* b_out = (const float*)d_in[3];
    const float* wl    = (const float*)d_in[4];
    float* out = (float*)d_out;

    (void)in_sizes; (void)n_in; (void)out_size;

    cudaFuncSetAttribute(attn_mma_kernel,
                         cudaFuncAttributeMaxDynamicSharedMemorySize, SMA_TOTAL);
    cudaFuncSetAttribute(qkv_mma_kernel,
                         cudaFuncAttributeMaxDynamicSharedMemorySize, GSM_TOTAL);
    cudaFuncSetAttribute(out_mma_kernel,
                         cudaFuncAttributeMaxDynamicSharedMemorySize, GSM_TOTAL);

    split_x_kernel<<<dim3(NSEQ / 32, DIM / 32, BATCH), dim3(32, 8)>>>(x);
    prep_kernel<<<(3 * DIM * DIM / 4 + 255) / 256, 256>>>(w_qkv, w_out, wl);

    qkv_mma_kernel<<<dim3(3 * DIM / 64, NSEQ / 128, BATCH), 256, GSM_TOTAL>>>();
    attn_mma_kernel<<<dim3(NSEQ / 256, HEADS, BATCH), 256, SMA_TOTAL>>>();
    out_mma_kernel<<<dim3(DIM / 64, NSEQ / 128, BATCH), 256, GSM_TOTAL>>>(b_out, out);
}